// round 4
// baseline (speedup 1.0000x reference)
#include <cuda_runtime.h>
#include <math.h>
#include <stdint.h>

// ---------------- problem constants ----------------
#define SEQ   2048
#define DMODEL 768
#define NH    8
#define DQK   128
#define DV    192
#define QKV_N (NH*DQK + DQK + DV)   // 1344
#define FFI   1536
#define NP    256
#define DP    128
#define DPI   256
#define NPAIR2 (NP*NP)              // 65536
#define DEPTH 4
#define EPS_RMS 1.1920929e-07f
#define EPS_LN  1e-5f

// ---------------- scratch (static device globals; no runtime alloc) ----------------
__device__ float g_xn[SEQ*DMODEL];
__device__ float g_qkv[SEQ*QKV_N];
__device__ float g_q[NH*SEQ*DQK];
__device__ float g_k[SEQ*DQK];
__device__ float g_v[SEQ*DV];
__device__ float g_sim[(size_t)NH*SEQ*SEQ];          // 134 MB
__device__ float g_pbg[NPAIR2*DP];
__device__ float g_pb[NPAIR2*NH];
__device__ float g_attnout[SEQ*NH*DV];
__device__ float g_proj[SEQ*DMODEL];
__device__ float g_ffh[SEQ*FFI];
__device__ float g_pxn[NPAIR2*DP];
__device__ float g_pqk[NPAIR2*2*DP];
__device__ float g_pv[NPAIR2*DP];
__device__ float g_psim[(size_t)NP*NP*NP];           // 67 MB
__device__ float g_pffh[NPAIR2*DPI];

// ---------------- reductions ----------------
__device__ __forceinline__ float warp_sum(float v){
  #pragma unroll
  for (int o=16;o;o>>=1) v += __shfl_xor_sync(0xffffffffu, v, o);
  return v;
}
__device__ __forceinline__ float warp_max(float v){
  #pragma unroll
  for (int o=16;o;o>>=1) v = fmaxf(v, __shfl_xor_sync(0xffffffffu, v, o));
  return v;
}
__device__ __forceinline__ float blk_sum(float v, float* red){
  __syncthreads();
  int lane = threadIdx.x & 31, w = threadIdx.x >> 5;
  v = warp_sum(v);
  if (lane == 0) red[w] = v;
  __syncthreads();
  int nw = blockDim.x >> 5;
  float s = (threadIdx.x < nw) ? red[threadIdx.x] : 0.f;
  s = warp_sum(s);
  if (threadIdx.x == 0) red[0] = s;
  __syncthreads();
  return red[0];
}
__device__ __forceinline__ float blk_max(float v, float* red){
  __syncthreads();
  int lane = threadIdx.x & 31, w = threadIdx.x >> 5;
  v = warp_max(v);
  if (lane == 0) red[w] = v;
  __syncthreads();
  int nw = blockDim.x >> 5;
  float s = (threadIdx.x < nw) ? red[threadIdx.x] : -3.0e38f;
  s = warp_max(s);
  if (threadIdx.x == 0) red[0] = s;
  __syncthreads();
  return red[0];
}

// =====================================================================
// 128x128 tiled SGEMM, 8x8 microtile per thread, kTile=16,
// double-buffered SMEM with register-staged global prefetch.
// Requirements guaranteed by call sites: K % 16 == 0, M % 128 == 0,
// lda/ldb/ldc % 4 == 0, N % 4 == 0, 16B-aligned base pointers.
// A: [M,K] (lda). B NN: [K,N] (ldb). B NT: [N,K] (ldb).
// batched via gridDim.z with element strides sA,sB,sC (res uses sC/ldc).
// =====================================================================
template<bool TB, bool BIAS, bool RELU, bool RES>
__global__ __launch_bounds__(256) void gemm128(
    const float* __restrict__ A, const float* __restrict__ B,
    const float* __restrict__ bias, const float* __restrict__ res,
    float* __restrict__ C,
    int M, int N, int K, int lda, int ldb, int ldc,
    long sA, long sB, long sC)
{
  __shared__ float As[2][16][128];
  __shared__ float Bs[2][16][128];
  int b = blockIdx.z;
  const float* Ab = A + (size_t)b * sA;
  const float* Bb = B + (size_t)b * sB;
  float* Cb = C + (size_t)b * sC;
  const float* Rb = RES ? (res + (size_t)b * sC) : nullptr;
  int m0 = blockIdx.y * 128, n0 = blockIdx.x * 128;
  int tid = threadIdx.x;
  int tx = tid & 15, ty = tid >> 4;

  // per-thread constant tile-load coordinates
  int ar[2], ac4[2], br[2], bc4[2];
  #pragma unroll
  for (int l = 0; l < 2; l++) {
    int idx = tid + l * 256;       // 0..511
    ar[l]  = idx >> 2;             // A m-row 0..127
    ac4[l] = (idx & 3) * 4;        // A k offset 0,4,8,12
    if (!TB) {
      br[l]  = idx >> 5;           // B k 0..15
      bc4[l] = (idx & 31) * 4;     // B n 0..124
    } else {
      br[l]  = idx >> 2;           // B n 0..127
      bc4[l] = (idx & 3) * 4;      // B k offset
    }
  }

  float4 fa[2], fb[2];
  // ---- fetch tile k0 into regs ----
  auto fetch = [&](int k0) {
    #pragma unroll
    for (int l = 0; l < 2; l++)
      fa[l] = *(const float4*)&Ab[(size_t)(m0 + ar[l]) * lda + k0 + ac4[l]];
    #pragma unroll
    for (int l = 0; l < 2; l++) {
      if (!TB) {
        fb[l] = (n0 + bc4[l] < N)
              ? *(const float4*)&Bb[(size_t)(k0 + br[l]) * ldb + n0 + bc4[l]]
              : make_float4(0.f, 0.f, 0.f, 0.f);
      } else {
        fb[l] = (n0 + br[l] < N)
              ? *(const float4*)&Bb[(size_t)(n0 + br[l]) * ldb + k0 + bc4[l]]
              : make_float4(0.f, 0.f, 0.f, 0.f);
      }
    }
  };
  // ---- store regs into smem buffer ----
  auto store = [&](int buf) {
    #pragma unroll
    for (int l = 0; l < 2; l++) {
      As[buf][ac4[l] + 0][ar[l]] = fa[l].x;
      As[buf][ac4[l] + 1][ar[l]] = fa[l].y;
      As[buf][ac4[l] + 2][ar[l]] = fa[l].z;
      As[buf][ac4[l] + 3][ar[l]] = fa[l].w;
    }
    #pragma unroll
    for (int l = 0; l < 2; l++) {
      if (!TB) {
        *(float4*)&Bs[buf][br[l]][bc4[l]] = fb[l];
      } else {
        Bs[buf][bc4[l] + 0][br[l]] = fb[l].x;
        Bs[buf][bc4[l] + 1][br[l]] = fb[l].y;
        Bs[buf][bc4[l] + 2][br[l]] = fb[l].z;
        Bs[buf][bc4[l] + 3][br[l]] = fb[l].w;
      }
    }
  };

  float acc[8][8] = {};
  fetch(0);
  store(0);
  __syncthreads();
  int buf = 0;
  for (int k0 = 0; k0 < K; k0 += 16) {
    bool more = (k0 + 16) < K;
    if (more) fetch(k0 + 16);          // LDG overlapped with compute below
    #pragma unroll
    for (int kk = 0; kk < 16; kk++) {
      float a[8], bb[8];
      *(float4*)&a[0]  = *(const float4*)&As[buf][kk][ty * 8];
      *(float4*)&a[4]  = *(const float4*)&As[buf][kk][ty * 8 + 4];
      *(float4*)&bb[0] = *(const float4*)&Bs[buf][kk][tx * 8];
      *(float4*)&bb[4] = *(const float4*)&Bs[buf][kk][tx * 8 + 4];
      #pragma unroll
      for (int i = 0; i < 8; i++)
        #pragma unroll
        for (int j = 0; j < 8; j++)
          acc[i][j] += a[i] * bb[j];
    }
    if (more) store(buf ^ 1);
    __syncthreads();
    buf ^= 1;
  }

  #pragma unroll
  for (int i = 0; i < 8; i++) {
    int m = m0 + ty * 8 + i;
    #pragma unroll
    for (int j = 0; j < 8; j++) {
      int n = n0 + tx * 8 + j;
      if (n >= N) continue;
      float v = acc[i][j];
      if (BIAS) v += bias[n];
      if (RELU) v = fmaxf(v, 0.f);
      if (RES)  v += Rb[(size_t)m * ldc + n];
      Cb[(size_t)m * ldc + n] = v;
    }
  }
}

static inline dim3 grid128(int M, int N, int batch) {
  return dim3((unsigned)((N + 127) / 128), (unsigned)((M + 127) / 128), (unsigned)batch);
}

// ---------------- 64x64 tile SGEMM (kept for tiny-N: pairwise-bias proj N=8) ----------
template<bool TB, bool BIAS, bool RELU, bool RES>
__global__ __launch_bounds__(256) void gemm64(
    const float* __restrict__ A, const float* __restrict__ B,
    const float* __restrict__ bias, const float* __restrict__ res,
    float* __restrict__ C,
    int M, int N, int K, int lda, int ldb, int ldc,
    long sA, long sB, long sC)
{
  __shared__ float As[16][64];
  __shared__ float Bs[16][64];
  int b = blockIdx.z;
  const float* Ab = A + (size_t)b * sA;
  const float* Bb = B + (size_t)b * sB;
  float* Cb = C + (size_t)b * sC;
  const float* Rb = RES ? (res + (size_t)b * sC) : nullptr;
  int m0 = blockIdx.y * 64, n0 = blockIdx.x * 64;
  int tid = threadIdx.x;
  int tx = tid & 15, ty = tid >> 4;
  float acc[4][4] = {};
  for (int k0 = 0; k0 < K; k0 += 16) {
    #pragma unroll
    for (int l = 0; l < 4; l++) {
      int idx = tid + l * 256;
      int r = idx >> 4, c = idx & 15;
      int m = m0 + r, k = k0 + c;
      As[c][r] = (m < M && k < K) ? Ab[(size_t)m * lda + k] : 0.f;
    }
    #pragma unroll
    for (int l = 0; l < 4; l++) {
      int idx = tid + l * 256;
      if (!TB) {
        int r = idx >> 6, c = idx & 63;
        int k = k0 + r, n = n0 + c;
        Bs[r][c] = (k < K && n < N) ? Bb[(size_t)k * ldb + n] : 0.f;
      } else {
        int nn = idx >> 4, kk = idx & 15;
        int n = n0 + nn, k = k0 + kk;
        Bs[kk][nn] = (n < N && k < K) ? Bb[(size_t)n * ldb + k] : 0.f;
      }
    }
    __syncthreads();
    #pragma unroll
    for (int kk = 0; kk < 16; kk++) {
      float a[4], bb[4];
      #pragma unroll
      for (int i = 0; i < 4; i++) a[i] = As[kk][ty * 4 + i];
      #pragma unroll
      for (int j = 0; j < 4; j++) bb[j] = Bs[kk][tx * 4 + j];
      #pragma unroll
      for (int i = 0; i < 4; i++)
        #pragma unroll
        for (int j = 0; j < 4; j++)
          acc[i][j] += a[i] * bb[j];
    }
    __syncthreads();
  }
  #pragma unroll
  for (int i = 0; i < 4; i++) {
    int m = m0 + ty * 4 + i;
    if (m >= M) continue;
    #pragma unroll
    for (int j = 0; j < 4; j++) {
      int n = n0 + tx * 4 + j;
      if (n >= N) continue;
      float v = acc[i][j];
      if (BIAS) v += bias[n];
      if (RELU) v = fmaxf(v, 0.f);
      if (RES)  v += Rb[(size_t)m * ldc + n];
      Cb[(size_t)m * ldc + n] = v;
    }
  }
}

static inline dim3 grid64(int M, int N, int batch) {
  return dim3((unsigned)((N + 63) / 64), (unsigned)((M + 63) / 64), (unsigned)batch);
}

// ---------------- norms ----------------
__global__ void rmsnorm_k(const float* __restrict__ x, const float* __restrict__ w,
                          float* __restrict__ y, int cols) {
  __shared__ float red[32];
  size_t row = blockIdx.x;
  const float* xr = x + row * cols;
  float s = 0.f;
  for (int c = threadIdx.x; c < cols; c += blockDim.x) { float v = xr[c]; s += v * v; }
  s = blk_sum(s, red);
  float inv = rsqrtf(s / (float)cols + EPS_RMS);
  for (int c = threadIdx.x; c < cols; c += blockDim.x)
    y[row * cols + c] = xr[c] * inv * w[c];
}

// y = rmsnorm(x)*w + res   (y may alias res)
__global__ void rmsnorm_add_k(const float* __restrict__ x, const float* __restrict__ w,
                              const float* __restrict__ res, float* __restrict__ y, int cols) {
  __shared__ float red[32];
  size_t row = blockIdx.x;
  const float* xr = x + row * cols;
  float s = 0.f;
  for (int c = threadIdx.x; c < cols; c += blockDim.x) { float v = xr[c]; s += v * v; }
  s = blk_sum(s, red);
  float inv = rsqrtf(s / (float)cols + EPS_RMS);
  for (int c = threadIdx.x; c < cols; c += blockDim.x)
    y[row * cols + c] = xr[c] * inv * w[c] + res[row * cols + c];
}

// y = gelu_exact(rmsnorm(x)*w)
__global__ void rmsgelu_k(const float* __restrict__ x, const float* __restrict__ w,
                          float* __restrict__ y, int cols) {
  __shared__ float red[32];
  size_t row = blockIdx.x;
  const float* xr = x + row * cols;
  float s = 0.f;
  for (int c = threadIdx.x; c < cols; c += blockDim.x) { float v = xr[c]; s += v * v; }
  s = blk_sum(s, red);
  float inv = rsqrtf(s / (float)cols + EPS_RMS);
  for (int c = threadIdx.x; c < cols; c += blockDim.x) {
    float v = xr[c] * inv * w[c];
    y[row * cols + c] = 0.5f * v * (1.0f + erff(v * 0.70710678118654752f));
  }
}

// ---------------- q/k/v post-processing (layernorm no-bias [+scale] [+rotary]) --------
// Reference inv_freq = 1/(j + 10^(1 + j*8128/63)) in fp32: 10^e overflows to inf
// for every j >= 1, so inv_freq = [0.1, 0, 0, ...]. Only dims 0 and 64 rotate.
__global__ void q_post_k(const float* __restrict__ qkv, const float* __restrict__ w,
                         float* __restrict__ qout) {
  __shared__ float red[32];
  __shared__ float sm[DQK];
  int i = blockIdx.x, h = blockIdx.y, d = threadIdx.x;   // 128 threads
  const float* xr = qkv + (size_t)i * QKV_N + h * DQK;
  float v = xr[d];
  float mu = blk_sum(v, red) * (1.0f / DQK);
  float dv = v - mu;
  float var = blk_sum(dv * dv, red) * (1.0f / DQK);
  float nv = dv * rsqrtf(var + EPS_LN) * w[d] * 0.125f;   // SCALE = 64^-0.5
  sm[d] = nv;
  __syncthreads();
  float out;
  if ((d & 63) == 0) {
    float rot = (d < 64) ? -sm[d + 64] : sm[d - 64];
    float ang = (float)i * 0.1f;
    out = nv * cosf(ang) + rot * sinf(ang);
  } else {
    out = nv;
  }
  qout[((size_t)h * SEQ + i) * DQK + d] = out;
}

__global__ void k_post_k(const float* __restrict__ qkv, const float* __restrict__ w,
                         float* __restrict__ kout) {
  __shared__ float red[32];
  __shared__ float sm[DQK];
  int i = blockIdx.x, d = threadIdx.x;
  const float* xr = qkv + (size_t)i * QKV_N + NH * DQK;
  float v = xr[d];
  float mu = blk_sum(v, red) * (1.0f / DQK);
  float dv = v - mu;
  float var = blk_sum(dv * dv, red) * (1.0f / DQK);
  float nv = dv * rsqrtf(var + EPS_LN) * w[d];
  sm[d] = nv;
  __syncthreads();
  float out;
  if ((d & 63) == 0) {
    float rot = (d < 64) ? -sm[d + 64] : sm[d - 64];
    float ang = (float)i * 0.1f;
    out = nv * cosf(ang) + rot * sinf(ang);
  } else {
    out = nv;
  }
  kout[(size_t)i * DQK + d] = out;
}

__global__ void v_post_k(const float* __restrict__ qkv, const float* __restrict__ w,
                         float* __restrict__ vout) {
  __shared__ float red[32];
  int i = blockIdx.x, d = threadIdx.x;   // 192 threads
  const float* xr = qkv + (size_t)i * QKV_N + NH * DQK + DQK;
  float v = xr[d];
  float mu = blk_sum(v, red) * (1.0f / DV);
  float dv = v - mu;
  float var = blk_sum(dv * dv, red) * (1.0f / DV);
  vout[(size_t)i * DV + d] = dv * rsqrtf(var + EPS_LN) * w[d];
}

// ---------------- softmax(softclamp(sim + bias)) in-place, float4-vectorized ----------
// Bias index j>>3 is constant within each aligned 4-group (j4*4..j4*4+3 -> j4>>1),
// so one bias load serves each float4.
__global__ void attn_softmax_k(float* __restrict__ sim, const float* __restrict__ pb) {
  __shared__ float4 sm4[SEQ / 4];   // 8 KB
  __shared__ float red[32];
  int i = blockIdx.x, h = blockIdx.y;
  float4* row4 = (float4*)(sim + ((size_t)h * SEQ + i) * SEQ);
  int pi = i >> 3;
  const float* pbrow = pb + (size_t)pi * NP * NH + h;
  float lmax = -3.0e38f;
  for (int j4 = threadIdx.x; j4 < SEQ / 4; j4 += blockDim.x) {
    float bias = pbrow[(size_t)(j4 >> 1) * NH];
    float4 v = row4[j4];
    v.x = 5.0f * tanhf((v.x + bias) * 0.2f);
    v.y = 5.0f * tanhf((v.y + bias) * 0.2f);
    v.z = 5.0f * tanhf((v.z + bias) * 0.2f);
    v.w = 5.0f * tanhf((v.w + bias) * 0.2f);
    sm4[j4] = v;
    lmax = fmaxf(lmax, fmaxf(fmaxf(v.x, v.y), fmaxf(v.z, v.w)));
  }
  float gmax = blk_max(lmax, red);
  float lsum = 0.f;
  for (int j4 = threadIdx.x; j4 < SEQ / 4; j4 += blockDim.x) {
    float4 v = sm4[j4];
    v.x = expf(v.x - gmax);
    v.y = expf(v.y - gmax);
    v.z = expf(v.z - gmax);
    v.w = expf(v.w - gmax);
    sm4[j4] = v;
    lsum += v.x + v.y + v.z + v.w;
  }
  float gsum = blk_sum(lsum, red);
  float inv = 1.0f / gsum;
  for (int j4 = threadIdx.x; j4 < SEQ / 4; j4 += blockDim.x) {
    float4 v = sm4[j4];
    v.x *= inv; v.y *= inv; v.z *= inv; v.w *= inv;
    row4[j4] = v;
  }
}

// ---------------- softmax in-place, row length NP (pairwise) ----------------
__global__ void psoftmax_k(float* __restrict__ psim) {
  __shared__ float red[32];
  size_t row = blockIdx.x;
  float* r = psim + row * NP;
  float v = r[threadIdx.x];            // 256 threads, one element each
  float gmax = blk_max(v, red);
  float e = expf(v - gmax);
  float gsum = blk_sum(e, red);
  r[threadIdx.x] = e / gsum;
}

// ---------------- host driver ----------------
extern "C" void kernel_launch(void* const* d_in, const int* in_sizes, int n_in,
                              void* d_out, int out_size) {
  (void)in_sizes; (void)n_in; (void)out_size;
  const float* in_single     = (const float*)d_in[0];
  const float* in_pairwise   = (const float*)d_in[1];
  const float* attn_pre_w    = (const float*)d_in[2];
  const float* attn_post_w   = (const float*)d_in[3];
  const float* qkv_w         = (const float*)d_in[4];
  const float* q_norm_w      = (const float*)d_in[5];
  const float* k_norm_w      = (const float*)d_in[6];
  const float* v_norm_w      = (const float*)d_in[7];
  const float* bias_rms_w    = (const float*)d_in[8];
  const float* bias_proj_w   = (const float*)d_in[9];
  const float* out_w         = (const float*)d_in[10];
  const float* ff_pre_w      = (const float*)d_in[11];
  const float* ff_post_w     = (const float*)d_in[12];
  const float* ff_w1         = (const float*)d_in[13];
  const float* ff_b1         = (const float*)d_in[14];
  const float* ff_w2         = (const float*)d_in[15];
  const float* ff_b2         = (const float*)d_in[16];
  const float* pw_attn_pre_w = (const float*)d_in[17];
  const float* pw_qk_w       = (const float*)d_in[18];
  const float* pw_v_w        = (const float*)d_in[19];
  const float* pw_v_b        = (const float*)d_in[20];
  const float* pw_ff_pre_w   = (const float*)d_in[21];
  const float* pw_ff_w1      = (const float*)d_in[22];
  const float* pw_ff_b1      = (const float*)d_in[23];
  const float* pw_ff_w2      = (const float*)d_in[24];
  const float* pw_ff_b2      = (const float*)d_in[25];

  float* s_state = (float*)d_out;                        // single [SEQ, DMODEL]
  float* p_state = (float*)d_out + (size_t)SEQ * DMODEL; // pairwise [NPAIR2, DP]

  cudaMemcpyAsync(s_state, in_single,   sizeof(float) * (size_t)SEQ * DMODEL,
                  cudaMemcpyDeviceToDevice);
  cudaMemcpyAsync(p_state, in_pairwise, sizeof(float) * (size_t)NPAIR2 * DP,
                  cudaMemcpyDeviceToDevice);

  float *xn, *qkv, *q, *k, *v, *sim, *pbg, *pb, *attnout, *proj, *ffh;
  float *pxn, *pqk, *pv, *psim, *pffh;
  cudaGetSymbolAddress((void**)&xn, g_xn);
  cudaGetSymbolAddress((void**)&qkv, g_qkv);
  cudaGetSymbolAddress((void**)&q, g_q);
  cudaGetSymbolAddress((void**)&k, g_k);
  cudaGetSymbolAddress((void**)&v, g_v);
  cudaGetSymbolAddress((void**)&sim, g_sim);
  cudaGetSymbolAddress((void**)&pbg, g_pbg);
  cudaGetSymbolAddress((void**)&pb, g_pb);
  cudaGetSymbolAddress((void**)&attnout, g_attnout);
  cudaGetSymbolAddress((void**)&proj, g_proj);
  cudaGetSymbolAddress((void**)&ffh, g_ffh);
  cudaGetSymbolAddress((void**)&pxn, g_pxn);
  cudaGetSymbolAddress((void**)&pqk, g_pqk);
  cudaGetSymbolAddress((void**)&pv, g_pv);
  cudaGetSymbolAddress((void**)&psim, g_psim);
  cudaGetSymbolAddress((void**)&pffh, g_pffh);

  int pw_idx = 0;
  for (int i = 0; i < DEPTH; i++) {
    // ===================== single-track attention =====================
    rmsnorm_k<<<SEQ, 256>>>(s_state, attn_pre_w + i * DMODEL, xn, DMODEL);

    gemm128<false,false,false,false><<<grid128(SEQ, QKV_N, 1), 256>>>(
        xn, qkv_w + (size_t)i * DMODEL * QKV_N, nullptr, nullptr, qkv,
        SEQ, QKV_N, DMODEL, DMODEL, QKV_N, QKV_N, 0, 0, 0);

    q_post_k<<<dim3(SEQ, NH), DQK>>>(qkv, q_norm_w + i * DQK, q);
    k_post_k<<<SEQ, DQK>>>(qkv, k_norm_w + i * DQK, k);
    v_post_k<<<SEQ, DV>>>(qkv, v_norm_w + i * DV, v);

    // pairwise bias: gelu(rmsnorm(pairwise)) @ proj -> [NPAIR2, NH]
    rmsgelu_k<<<NPAIR2, 128>>>(p_state, bias_rms_w + i * DP, pbg, DP);
    gemm64<false,false,false,false><<<grid64(NPAIR2, NH, 1), 256>>>(
        pbg, bias_proj_w + (size_t)i * DP * NH, nullptr, nullptr, pb,
        NPAIR2, NH, DP, DP, NH, NH, 0, 0, 0);

    // sim[h] = q[h] @ k^T   (batched NT)
    gemm128<true,false,false,false><<<grid128(SEQ, SEQ, NH), 256>>>(
        q, k, nullptr, nullptr, sim,
        SEQ, SEQ, DQK, DQK, DQK, SEQ,
        (long)SEQ * DQK, 0, (long)SEQ * SEQ);

    attn_softmax_k<<<dim3(SEQ, NH), 256>>>(sim, pb);

    // attnout[i, h*DV+d] = attn[h] @ v   (batched NN, strided C)
    gemm128<false,false,false,false><<<grid128(SEQ, DV, NH), 256>>>(
        sim, v, nullptr, nullptr, attnout,
        SEQ, DV, SEQ, SEQ, DV, NH * DV,
        (long)SEQ * SEQ, 0, (long)DV);

    gemm128<false,false,false,false><<<grid128(SEQ, DMODEL, 1), 256>>>(
        attnout, out_w + (size_t)i * (NH * DV) * DMODEL, nullptr, nullptr, proj,
        SEQ, DMODEL, NH * DV, NH * DV, DMODEL, DMODEL, 0, 0, 0);

    rmsnorm_add_k<<<SEQ, 256>>>(proj, attn_post_w + i * DMODEL, s_state, s_state, DMODEL);

    // ===================== single-track feedforward =====================
    rmsnorm_k<<<SEQ, 256>>>(s_state, ff_pre_w + i * DMODEL, xn, DMODEL);
    gemm128<false,true,true,false><<<grid128(SEQ, FFI, 1), 256>>>(
        xn, ff_w1 + (size_t)i * DMODEL * FFI, ff_b1 + i * FFI, nullptr, ffh,
        SEQ, FFI, DMODEL, DMODEL, FFI, FFI, 0, 0, 0);
    gemm128<false,true,false,false><<<grid128(SEQ, DMODEL, 1), 256>>>(
        ffh, ff_w2 + (size_t)i * FFI * DMODEL, ff_b2 + i * DMODEL, nullptr, proj,
        SEQ, DMODEL, FFI, FFI, DMODEL, DMODEL, 0, 0, 0);
    rmsnorm_add_k<<<SEQ, 256>>>(proj, ff_post_w + i * DMODEL, s_state, s_state, DMODEL);

    // ===================== pairwise track (every other layer) =====================
    if (i % 2 == 0) {
      int j = pw_idx++;
      // attention over pairwise rows
      rmsnorm_k<<<NPAIR2, 128>>>(p_state, pw_attn_pre_w + j * DP, pxn, DP);
      gemm128<false,false,false,false><<<grid128(NPAIR2, 2 * DP, 1), 256>>>(
          pxn, pw_qk_w + (size_t)j * DP * 2 * DP, nullptr, nullptr, pqk,
          NPAIR2, 2 * DP, DP, DP, 2 * DP, 2 * DP, 0, 0, 0);
      gemm128<false,true,false,false><<<grid128(NPAIR2, DP, 1), 256>>>(
          pxn, pw_v_w + (size_t)j * DP * DP, pw_v_b + j * DP, nullptr, pv,
          NPAIR2, DP, DP, DP, DP, DP, 0, 0, 0);
      // psim[n] = pq[n] @ pk[n]^T  (batched NT; pq/pk interleaved in pqk, ld=256)
      gemm128<true,false,false,false><<<grid128(NP, NP, NP), 256>>>(
          pqk, pqk + DP, nullptr, nullptr, psim,
          NP, NP, DP, 2 * DP, 2 * DP, NP,
          (long)NP * 2 * DP, (long)NP * 2 * DP, (long)NP * NP);
      psoftmax_k<<<NPAIR2, NP>>>(psim);
      // pairwise = attn @ pv + pairwise   (batched NN with residual, in place)
      gemm128<false,false,false,true><<<grid128(NP, DP, NP), 256>>>(
          psim, pv, nullptr, p_state, p_state,
          NP, DP, NP, NP, DP, DP,
          (long)NP * NP, (long)NP * DP, (long)NP * DP);
      // pairwise feedforward (no sandwich): pairwise = relu(rms(x)W1+b1)W2+b2 + res
      rmsnorm_k<<<NPAIR2, 128>>>(p_state, pw_ff_pre_w + j * DP, pxn, DP);
      gemm128<false,true,true,false><<<grid128(NPAIR2, DPI, 1), 256>>>(
          pxn, pw_ff_w1 + (size_t)j * DP * DPI, pw_ff_b1 + j * DPI, nullptr, pffh,
          NPAIR2, DPI, DP, DP, DPI, DPI, 0, 0, 0);
      gemm128<false,true,false,true><<<grid128(NPAIR2, DP, 1), 256>>>(
          pffh, pw_ff_w2 + (size_t)j * DPI * DP, pw_ff_b2 + j * DP, p_state, p_state,
          NPAIR2, DP, DPI, DPI, DP, DP, 0, 0, 0);
    }
  }
}

// round 17
// speedup vs baseline: 1.3653x; 1.3653x over previous
#include <cuda_runtime.h>
#include <math.h>
#include <stdint.h>

// ---------------- problem constants ----------------
#define SEQ   2048
#define DMODEL 768
#define NH    8
#define DQK   128
#define DV    192
#define QKV_N (NH*DQK + DQK + DV)   // 1344
#define FFI   1536
#define NP    256
#define DP    128
#define DPI   256
#define NPAIR2 (NP*NP)              // 65536
#define DEPTH 4
#define EPS_RMS 1.1920929e-07f
#define EPS_LN  1e-5f

// ---------------- scratch (static device globals; no runtime alloc) ----------------
__device__ float g_xn[SEQ*DMODEL];
__device__ float g_qkv[SEQ*QKV_N];
__device__ float g_q[NH*SEQ*DQK];
__device__ float g_k[SEQ*DQK];
__device__ float g_v[SEQ*DV];
__device__ float g_sim[(size_t)NH*SEQ*SEQ];          // 134 MB
__device__ float g_pbg[NPAIR2*DP];
__device__ float g_pb[NPAIR2*NH];
__device__ float g_attnout[SEQ*NH*DV];
__device__ float g_proj[SEQ*DMODEL];
__device__ float g_ffh[SEQ*FFI];
__device__ float g_pxn[NPAIR2*DP];
__device__ float g_pqk[NPAIR2*2*DP];
__device__ float g_pv[NPAIR2*DP];
__device__ float g_psim[(size_t)NP*NP*NP];           // 67 MB
__device__ float g_pffh[NPAIR2*DPI];

// ---------------- reductions ----------------
__device__ __forceinline__ float warp_sum(float v){
  #pragma unroll
  for (int o=16;o;o>>=1) v += __shfl_xor_sync(0xffffffffu, v, o);
  return v;
}
__device__ __forceinline__ float warp_max(float v){
  #pragma unroll
  for (int o=16;o;o>>=1) v = fmaxf(v, __shfl_xor_sync(0xffffffffu, v, o));
  return v;
}
__device__ __forceinline__ float blk_sum(float v, float* red){
  __syncthreads();
  int lane = threadIdx.x & 31, w = threadIdx.x >> 5;
  v = warp_sum(v);
  if (lane == 0) red[w] = v;
  __syncthreads();
  int nw = blockDim.x >> 5;
  float s = (threadIdx.x < nw) ? red[threadIdx.x] : 0.f;
  s = warp_sum(s);
  if (threadIdx.x == 0) red[0] = s;
  __syncthreads();
  return red[0];
}
__device__ __forceinline__ float blk_max(float v, float* red){
  __syncthreads();
  int lane = threadIdx.x & 31, w = threadIdx.x >> 5;
  v = warp_max(v);
  if (lane == 0) red[w] = v;
  __syncthreads();
  int nw = blockDim.x >> 5;
  float s = (threadIdx.x < nw) ? red[threadIdx.x] : -3.0e38f;
  s = warp_max(s);
  if (threadIdx.x == 0) red[0] = s;
  __syncthreads();
  return red[0];
}

// ---------------- tf32 helpers ----------------
__device__ __forceinline__ float to_tf32(float x){
  uint32_t u;
  asm("cvt.rna.tf32.f32 %0, %1;" : "=r"(u) : "f"(x));
  return __uint_as_float(u);
}
__device__ __forceinline__ void mma_tf32(float* d, const uint32_t* a, const uint32_t* b){
  asm volatile(
    "mma.sync.aligned.m16n8k8.row.col.f32.tf32.tf32.f32 "
    "{%0,%1,%2,%3}, {%4,%5,%6,%7}, {%8,%9}, {%0,%1,%2,%3};\n"
    : "+f"(d[0]), "+f"(d[1]), "+f"(d[2]), "+f"(d[3])
    : "r"(a[0]), "r"(a[1]), "r"(a[2]), "r"(a[3]), "r"(b[0]), "r"(b[1]));
}

// =====================================================================
// TF32 tensor-core GEMM: 128x128 CTA tile, kTile=16, 8 warps (4m x 2n),
// each warp 32x64 via m16n8k8 mma. Double-buffered padded SMEM
// ([16][132]: pad 4 -> fragment LDS bank = (4c+g)%32, conflict-free).
// Requirements (guaranteed by call sites): K%16==0, M%128==0, N even,
// lda/ldb/ldc%4==0, 16B-aligned base pointers.
// A: [M,K] (lda). B NN: [K,N] (ldb). B NT: [N,K] (ldb).
// Batched via gridDim.z with element strides sA,sB,sC (res uses sC/ldc).
// =====================================================================
#define TCPAD 132
template<bool TB, bool BIAS, bool RELU, bool RES>
__global__ __launch_bounds__(256) void gemm_tc(
    const float* __restrict__ A, const float* __restrict__ B,
    const float* __restrict__ bias, const float* __restrict__ res,
    float* __restrict__ C,
    int M, int N, int K, int lda, int ldb, int ldc,
    long sA, long sB, long sC)
{
  __shared__ float As[2][16][TCPAD];
  __shared__ float Bs[2][16][TCPAD];
  int b = blockIdx.z;
  const float* Ab = A + (size_t)b * sA;
  const float* Bb = B + (size_t)b * sB;
  float* Cb = C + (size_t)b * sC;
  const float* Rb = RES ? (res + (size_t)b * sC) : nullptr;
  int m0 = blockIdx.y * 128, n0 = blockIdx.x * 128;
  int tid = threadIdx.x;
  int warp = tid >> 5, lane = tid & 31;
  int wm = warp >> 1, wn = warp & 1;        // warp grid 4 (m) x 2 (n)
  int g = lane >> 2, c = lane & 3;          // groupID / threadID-in-group

  // cooperative tile-load coordinates (512 float4 slots over 256 threads)
  int ar[2], ac4[2], br[2], bc4[2];
  #pragma unroll
  for (int l = 0; l < 2; l++) {
    int idx = tid + l * 256;
    ar[l]  = idx >> 2;             // A m-row 0..127
    ac4[l] = (idx & 3) * 4;        // A k offset 0,4,8,12
    if (!TB) {
      br[l]  = idx >> 5;           // B k 0..15
      bc4[l] = (idx & 31) * 4;     // B n 0..124
    } else {
      br[l]  = idx >> 2;           // B n 0..127
      bc4[l] = (idx & 3) * 4;      // B k offset
    }
  }

  float4 fa[2], fb[2];
  auto fetch = [&](int k0) {
    #pragma unroll
    for (int l = 0; l < 2; l++)
      fa[l] = *(const float4*)&Ab[(size_t)(m0 + ar[l]) * lda + k0 + ac4[l]];
    #pragma unroll
    for (int l = 0; l < 2; l++) {
      if (!TB) {
        fb[l] = (n0 + bc4[l] < N)
              ? *(const float4*)&Bb[(size_t)(k0 + br[l]) * ldb + n0 + bc4[l]]
              : make_float4(0.f, 0.f, 0.f, 0.f);
      } else {
        fb[l] = (n0 + br[l] < N)
              ? *(const float4*)&Bb[(size_t)(n0 + br[l]) * ldb + k0 + bc4[l]]
              : make_float4(0.f, 0.f, 0.f, 0.f);
      }
    }
  };
  auto store = [&](int buf) {
    #pragma unroll
    for (int l = 0; l < 2; l++) {
      As[buf][ac4[l] + 0][ar[l]] = to_tf32(fa[l].x);
      As[buf][ac4[l] + 1][ar[l]] = to_tf32(fa[l].y);
      As[buf][ac4[l] + 2][ar[l]] = to_tf32(fa[l].z);
      As[buf][ac4[l] + 3][ar[l]] = to_tf32(fa[l].w);
    }
    #pragma unroll
    for (int l = 0; l < 2; l++) {
      if (!TB) {
        Bs[buf][br[l]][bc4[l] + 0] = to_tf32(fb[l].x);
        Bs[buf][br[l]][bc4[l] + 1] = to_tf32(fb[l].y);
        Bs[buf][br[l]][bc4[l] + 2] = to_tf32(fb[l].z);
        Bs[buf][br[l]][bc4[l] + 3] = to_tf32(fb[l].w);
      } else {
        Bs[buf][bc4[l] + 0][br[l]] = to_tf32(fb[l].x);
        Bs[buf][bc4[l] + 1][br[l]] = to_tf32(fb[l].y);
        Bs[buf][bc4[l] + 2][br[l]] = to_tf32(fb[l].z);
        Bs[buf][bc4[l] + 3][br[l]] = to_tf32(fb[l].w);
      }
    }
  };

  float acc[2][8][4] = {};   // [m-subtile][n-subtile][c-regs]

  fetch(0);
  store(0);
  __syncthreads();
  int buf = 0;
  for (int k0 = 0; k0 < K; k0 += 16) {
    bool more = (k0 + 16) < K;
    if (more) fetch(k0 + 16);
    #pragma unroll
    for (int ks = 0; ks < 2; ks++) {
      int kk = ks * 8;
      uint32_t af[2][4], bf[8][2];
      #pragma unroll
      for (int mt = 0; mt < 2; mt++) {
        int rb = wm * 32 + mt * 16 + g;
        af[mt][0] = __float_as_uint(As[buf][kk + c    ][rb]);
        af[mt][1] = __float_as_uint(As[buf][kk + c    ][rb + 8]);
        af[mt][2] = __float_as_uint(As[buf][kk + c + 4][rb]);
        af[mt][3] = __float_as_uint(As[buf][kk + c + 4][rb + 8]);
      }
      #pragma unroll
      for (int nt = 0; nt < 8; nt++) {
        int cb = wn * 64 + nt * 8 + g;
        bf[nt][0] = __float_as_uint(Bs[buf][kk + c    ][cb]);
        bf[nt][1] = __float_as_uint(Bs[buf][kk + c + 4][cb]);
      }
      #pragma unroll
      for (int mt = 0; mt < 2; mt++)
        #pragma unroll
        for (int nt = 0; nt < 8; nt++)
          mma_tf32(acc[mt][nt], af[mt], bf[nt]);
    }
    if (more) store(buf ^ 1);
    __syncthreads();
    buf ^= 1;
  }

  // ---- epilogue: D rows g/g+8, cols 2c/2c+1 within each m16n8 subtile ----
  #pragma unroll
  for (int mt = 0; mt < 2; mt++) {
    int row0 = m0 + wm * 32 + mt * 16 + g;
    #pragma unroll
    for (int nt = 0; nt < 8; nt++) {
      int col = n0 + wn * 64 + nt * 8 + 2 * c;
      if (col >= N) continue;          // N even -> col+1 < N too
      float2 bval;
      if (BIAS) bval = *(const float2*)&bias[col];
      #pragma unroll
      for (int rr = 0; rr < 2; rr++) {
        int row = row0 + rr * 8;
        float vx = acc[mt][nt][rr * 2 + 0];
        float vy = acc[mt][nt][rr * 2 + 1];
        if (BIAS) { vx += bval.x; vy += bval.y; }
        if (RELU) { vx = fmaxf(vx, 0.f); vy = fmaxf(vy, 0.f); }
        if (RES) {
          float2 r2 = *(const float2*)&Rb[(size_t)row * ldc + col];
          vx += r2.x; vy += r2.y;
        }
        *(float2*)&Cb[(size_t)row * ldc + col] = make_float2(vx, vy);
      }
    }
  }
}

static inline dim3 grid128(int M, int N, int batch) {
  return dim3((unsigned)((N + 127) / 128), (unsigned)((M + 127) / 128), (unsigned)batch);
}

// ---------------- 64x64 tile FFMA SGEMM (tiny-N: pairwise-bias proj N=8) ----------
template<bool TB, bool BIAS, bool RELU, bool RES>
__global__ __launch_bounds__(256) void gemm64(
    const float* __restrict__ A, const float* __restrict__ B,
    const float* __restrict__ bias, const float* __restrict__ res,
    float* __restrict__ C,
    int M, int N, int K, int lda, int ldb, int ldc,
    long sA, long sB, long sC)
{
  __shared__ float As[16][64];
  __shared__ float Bs[16][64];
  int b = blockIdx.z;
  const float* Ab = A + (size_t)b * sA;
  const float* Bb = B + (size_t)b * sB;
  float* Cb = C + (size_t)b * sC;
  const float* Rb = RES ? (res + (size_t)b * sC) : nullptr;
  int m0 = blockIdx.y * 64, n0 = blockIdx.x * 64;
  int tid = threadIdx.x;
  int tx = tid & 15, ty = tid >> 4;
  float acc[4][4] = {};
  for (int k0 = 0; k0 < K; k0 += 16) {
    #pragma unroll
    for (int l = 0; l < 4; l++) {
      int idx = tid + l * 256;
      int r = idx >> 4, cc = idx & 15;
      int m = m0 + r, k = k0 + cc;
      As[cc][r] = (m < M && k < K) ? Ab[(size_t)m * lda + k] : 0.f;
    }
    #pragma unroll
    for (int l = 0; l < 4; l++) {
      int idx = tid + l * 256;
      if (!TB) {
        int r = idx >> 6, cc = idx & 63;
        int k = k0 + r, n = n0 + cc;
        Bs[r][cc] = (k < K && n < N) ? Bb[(size_t)k * ldb + n] : 0.f;
      } else {
        int nn = idx >> 4, kk = idx & 15;
        int n = n0 + nn, k = k0 + kk;
        Bs[kk][nn] = (n < N && k < K) ? Bb[(size_t)n * ldb + k] : 0.f;
      }
    }
    __syncthreads();
    #pragma unroll
    for (int kk = 0; kk < 16; kk++) {
      float a[4], bb[4];
      #pragma unroll
      for (int i = 0; i < 4; i++) a[i] = As[kk][ty * 4 + i];
      #pragma unroll
      for (int j = 0; j < 4; j++) bb[j] = Bs[kk][tx * 4 + j];
      #pragma unroll
      for (int i = 0; i < 4; i++)
        #pragma unroll
        for (int j = 0; j < 4; j++)
          acc[i][j] += a[i] * bb[j];
    }
    __syncthreads();
  }
  #pragma unroll
  for (int i = 0; i < 4; i++) {
    int m = m0 + ty * 4 + i;
    if (m >= M) continue;
    #pragma unroll
    for (int j = 0; j < 4; j++) {
      int n = n0 + tx * 4 + j;
      if (n >= N) continue;
      float v = acc[i][j];
      if (BIAS) v += bias[n];
      if (RELU) v = fmaxf(v, 0.f);
      if (RES)  v += Rb[(size_t)m * ldc + n];
      Cb[(size_t)m * ldc + n] = v;
    }
  }
}

static inline dim3 grid64(int M, int N, int batch) {
  return dim3((unsigned)((N + 63) / 64), (unsigned)((M + 63) / 64), (unsigned)batch);
}

// ---------------- norms ----------------
__global__ void rmsnorm_k(const float* __restrict__ x, const float* __restrict__ w,
                          float* __restrict__ y, int cols) {
  __shared__ float red[32];
  size_t row = blockIdx.x;
  const float* xr = x + row * cols;
  float s = 0.f;
  for (int c = threadIdx.x; c < cols; c += blockDim.x) { float v = xr[c]; s += v * v; }
  s = blk_sum(s, red);
  float inv = rsqrtf(s / (float)cols + EPS_RMS);
  for (int c = threadIdx.x; c < cols; c += blockDim.x)
    y[row * cols + c] = xr[c] * inv * w[c];
}

// y = rmsnorm(x)*w + res   (y may alias res)
__global__ void rmsnorm_add_k(const float* __restrict__ x, const float* __restrict__ w,
                              const float* __restrict__ res, float* __restrict__ y, int cols) {
  __shared__ float red[32];
  size_t row = blockIdx.x;
  const float* xr = x + row * cols;
  float s = 0.f;
  for (int c = threadIdx.x; c < cols; c += blockDim.x) { float v = xr[c]; s += v * v; }
  s = blk_sum(s, red);
  float inv = rsqrtf(s / (float)cols + EPS_RMS);
  for (int c = threadIdx.x; c < cols; c += blockDim.x)
    y[row * cols + c] = xr[c] * inv * w[c] + res[row * cols + c];
}

// y = gelu_exact(rmsnorm(x)*w)
__global__ void rmsgelu_k(const float* __restrict__ x, const float* __restrict__ w,
                          float* __restrict__ y, int cols) {
  __shared__ float red[32];
  size_t row = blockIdx.x;
  const float* xr = x + row * cols;
  float s = 0.f;
  for (int c = threadIdx.x; c < cols; c += blockDim.x) { float v = xr[c]; s += v * v; }
  s = blk_sum(s, red);
  float inv = rsqrtf(s / (float)cols + EPS_RMS);
  for (int c = threadIdx.x; c < cols; c += blockDim.x) {
    float v = xr[c] * inv * w[c];
    y[row * cols + c] = 0.5f * v * (1.0f + erff(v * 0.70710678118654752f));
  }
}

// ---------------- q/k/v post-processing (layernorm no-bias [+scale] [+rotary]) --------
// Reference inv_freq = 1/(j + 10^(1 + j*8128/63)) in fp32: 10^e overflows to inf
// for every j >= 1, so inv_freq = [0.1, 0, 0, ...]. Only dims 0 and 64 rotate.
__global__ void q_post_k(const float* __restrict__ qkv, const float* __restrict__ w,
                         float* __restrict__ qout) {
  __shared__ float red[32];
  __shared__ float sm[DQK];
  int i = blockIdx.x, h = blockIdx.y, d = threadIdx.x;   // 128 threads
  const float* xr = qkv + (size_t)i * QKV_N + h * DQK;
  float v = xr[d];
  float mu = blk_sum(v, red) * (1.0f / DQK);
  float dv = v - mu;
  float var = blk_sum(dv * dv, red) * (1.0f / DQK);
  float nv = dv * rsqrtf(var + EPS_LN) * w[d] * 0.125f;   // SCALE = 64^-0.5
  sm[d] = nv;
  __syncthreads();
  float out;
  if ((d & 63) == 0) {
    float rot = (d < 64) ? -sm[d + 64] : sm[d - 64];
    float ang = (float)i * 0.1f;
    out = nv * cosf(ang) + rot * sinf(ang);
  } else {
    out = nv;
  }
  qout[((size_t)h * SEQ + i) * DQK + d] = out;
}

__global__ void k_post_k(const float* __restrict__ qkv, const float* __restrict__ w,
                         float* __restrict__ kout) {
  __shared__ float red[32];
  __shared__ float sm[DQK];
  int i = blockIdx.x, d = threadIdx.x;
  const float* xr = qkv + (size_t)i * QKV_N + NH * DQK;
  float v = xr[d];
  float mu = blk_sum(v, red) * (1.0f / DQK);
  float dv = v - mu;
  float var = blk_sum(dv * dv, red) * (1.0f / DQK);
  float nv = dv * rsqrtf(var + EPS_LN) * w[d];
  sm[d] = nv;
  __syncthreads();
  float out;
  if ((d & 63) == 0) {
    float rot = (d < 64) ? -sm[d + 64] : sm[d - 64];
    float ang = (float)i * 0.1f;
    out = nv * cosf(ang) + rot * sinf(ang);
  } else {
    out = nv;
  }
  kout[(size_t)i * DQK + d] = out;
}

__global__ void v_post_k(const float* __restrict__ qkv, const float* __restrict__ w,
                         float* __restrict__ vout) {
  __shared__ float red[32];
  int i = blockIdx.x, d = threadIdx.x;   // 192 threads
  const float* xr = qkv + (size_t)i * QKV_N + NH * DQK + DQK;
  float v = xr[d];
  float mu = blk_sum(v, red) * (1.0f / DV);
  float dv = v - mu;
  float var = blk_sum(dv * dv, red) * (1.0f / DV);
  vout[(size_t)i * DV + d] = dv * rsqrtf(var + EPS_LN) * w[d];
}

// ---------------- softmax(softclamp(sim + bias)) in-place, float4-vectorized ----------
__global__ void attn_softmax_k(float* __restrict__ sim, const float* __restrict__ pb) {
  __shared__ float4 sm4[SEQ / 4];   // 8 KB
  __shared__ float red[32];
  int i = blockIdx.x, h = blockIdx.y;
  float4* row4 = (float4*)(sim + ((size_t)h * SEQ + i) * SEQ);
  int pi = i >> 3;
  const float* pbrow = pb + (size_t)pi * NP * NH + h;
  float lmax = -3.0e38f;
  for (int j4 = threadIdx.x; j4 < SEQ / 4; j4 += blockDim.x) {
    float bias = pbrow[(size_t)(j4 >> 1) * NH];
    float4 v = row4[j4];
    v.x = 5.0f * tanhf((v.x + bias) * 0.2f);
    v.y = 5.0f * tanhf((v.y + bias) * 0.2f);
    v.z = 5.0f * tanhf((v.z + bias) * 0.2f);
    v.w = 5.0f * tanhf((v.w + bias) * 0.2f);
    sm4[j4] = v;
    lmax = fmaxf(lmax, fmaxf(fmaxf(v.x, v.y), fmaxf(v.z, v.w)));
  }
  float gmax = blk_max(lmax, red);
  float lsum = 0.f;
  for (int j4 = threadIdx.x; j4 < SEQ / 4; j4 += blockDim.x) {
    float4 v = sm4[j4];
    v.x = expf(v.x - gmax);
    v.y = expf(v.y - gmax);
    v.z = expf(v.z - gmax);
    v.w = expf(v.w - gmax);
    sm4[j4] = v;
    lsum += v.x + v.y + v.z + v.w;
  }
  float gsum = blk_sum(lsum, red);
  float inv = 1.0f / gsum;
  for (int j4 = threadIdx.x; j4 < SEQ / 4; j4 += blockDim.x) {
    float4 v = sm4[j4];
    v.x *= inv; v.y *= inv; v.z *= inv; v.w *= inv;
    row4[j4] = v;
  }
}

// ---------------- softmax in-place, row length NP (pairwise) ----------------
__global__ void psoftmax_k(float* __restrict__ psim) {
  __shared__ float red[32];
  size_t row = blockIdx.x;
  float* r = psim + row * NP;
  float v = r[threadIdx.x];            // 256 threads, one element each
  float gmax = blk_max(v, red);
  float e = expf(v - gmax);
  float gsum = blk_sum(e, red);
  r[threadIdx.x] = e / gsum;
}

// ---------------- host driver ----------------
extern "C" void kernel_launch(void* const* d_in, const int* in_sizes, int n_in,
                              void* d_out, int out_size) {
  (void)in_sizes; (void)n_in; (void)out_size;
  const float* in_single     = (const float*)d_in[0];
  const float* in_pairwise   = (const float*)d_in[1];
  const float* attn_pre_w    = (const float*)d_in[2];
  const float* attn_post_w   = (const float*)d_in[3];
  const float* qkv_w         = (const float*)d_in[4];
  const float* q_norm_w      = (const float*)d_in[5];
  const float* k_norm_w      = (const float*)d_in[6];
  const float* v_norm_w      = (const float*)d_in[7];
  const float* bias_rms_w    = (const float*)d_in[8];
  const float* bias_proj_w   = (const float*)d_in[9];
  const float* out_w         = (const float*)d_in[10];
  const float* ff_pre_w      = (const float*)d_in[11];
  const float* ff_post_w     = (const float*)d_in[12];
  const float* ff_w1         = (const float*)d_in[13];
  const float* ff_b1         = (const float*)d_in[14];
  const float* ff_w2         = (const float*)d_in[15];
  const float* ff_b2         = (const float*)d_in[16];
  const float* pw_attn_pre_w = (const float*)d_in[17];
  const float* pw_qk_w       = (const float*)d_in[18];
  const float* pw_v_w        = (const float*)d_in[19];
  const float* pw_v_b        = (const float*)d_in[20];
  const float* pw_ff_pre_w   = (const float*)d_in[21];
  const float* pw_ff_w1      = (const float*)d_in[22];
  const float* pw_ff_b1      = (const float*)d_in[23];
  const float* pw_ff_w2      = (const float*)d_in[24];
  const float* pw_ff_b2      = (const float*)d_in[25];

  float* s_state = (float*)d_out;                        // single [SEQ, DMODEL]
  float* p_state = (float*)d_out + (size_t)SEQ * DMODEL; // pairwise [NPAIR2, DP]

  cudaMemcpyAsync(s_state, in_single,   sizeof(float) * (size_t)SEQ * DMODEL,
                  cudaMemcpyDeviceToDevice);
  cudaMemcpyAsync(p_state, in_pairwise, sizeof(float) * (size_t)NPAIR2 * DP,
                  cudaMemcpyDeviceToDevice);

  float *xn, *qkv, *q, *k, *v, *sim, *pbg, *pb, *attnout, *proj, *ffh;
  float *pxn, *pqk, *pv, *psim, *pffh;
  cudaGetSymbolAddress((void**)&xn, g_xn);
  cudaGetSymbolAddress((void**)&qkv, g_qkv);
  cudaGetSymbolAddress((void**)&q, g_q);
  cudaGetSymbolAddress((void**)&k, g_k);
  cudaGetSymbolAddress((void**)&v, g_v);
  cudaGetSymbolAddress((void**)&sim, g_sim);
  cudaGetSymbolAddress((void**)&pbg, g_pbg);
  cudaGetSymbolAddress((void**)&pb, g_pb);
  cudaGetSymbolAddress((void**)&attnout, g_attnout);
  cudaGetSymbolAddress((void**)&proj, g_proj);
  cudaGetSymbolAddress((void**)&ffh, g_ffh);
  cudaGetSymbolAddress((void**)&pxn, g_pxn);
  cudaGetSymbolAddress((void**)&pqk, g_pqk);
  cudaGetSymbolAddress((void**)&pv, g_pv);
  cudaGetSymbolAddress((void**)&psim, g_psim);
  cudaGetSymbolAddress((void**)&pffh, g_pffh);

  int pw_idx = 0;
  for (int i = 0; i < DEPTH; i++) {
    // ===================== single-track attention =====================
    rmsnorm_k<<<SEQ, 256>>>(s_state, attn_pre_w + i * DMODEL, xn, DMODEL);

    gemm_tc<false,false,false,false><<<grid128(SEQ, QKV_N, 1), 256>>>(
        xn, qkv_w + (size_t)i * DMODEL * QKV_N, nullptr, nullptr, qkv,
        SEQ, QKV_N, DMODEL, DMODEL, QKV_N, QKV_N, 0, 0, 0);

    q_post_k<<<dim3(SEQ, NH), DQK>>>(qkv, q_norm_w + i * DQK, q);
    k_post_k<<<SEQ, DQK>>>(qkv, k_norm_w + i * DQK, k);
    v_post_k<<<SEQ, DV>>>(qkv, v_norm_w + i * DV, v);

    // pairwise bias: gelu(rmsnorm(pairwise)) @ proj -> [NPAIR2, NH]
    rmsgelu_k<<<NPAIR2, 128>>>(p_state, bias_rms_w + i * DP, pbg, DP);
    gemm64<false,false,false,false><<<grid64(NPAIR2, NH, 1), 256>>>(
        pbg, bias_proj_w + (size_t)i * DP * NH, nullptr, nullptr, pb,
        NPAIR2, NH, DP, DP, NH, NH, 0, 0, 0);

    // sim[h] = q[h] @ k^T   (batched NT)
    gemm_tc<true,false,false,false><<<grid128(SEQ, SEQ, NH), 256>>>(
        q, k, nullptr, nullptr, sim,
        SEQ, SEQ, DQK, DQK, DQK, SEQ,
        (long)SEQ * DQK, 0, (long)SEQ * SEQ);

    attn_softmax_k<<<dim3(SEQ, NH), 256>>>(sim, pb);

    // attnout[i, h*DV+d] = attn[h] @ v   (batched NN, strided C)
    gemm_tc<false,false,false,false><<<grid128(SEQ, DV, NH), 256>>>(
        sim, v, nullptr, nullptr, attnout,
        SEQ, DV, SEQ, SEQ, DV, NH * DV,
        (long)SEQ * SEQ, 0, (long)DV);

    gemm_tc<false,false,false,false><<<grid128(SEQ, DMODEL, 1), 256>>>(
        attnout, out_w + (size_t)i * (NH * DV) * DMODEL, nullptr, nullptr, proj,
        SEQ, DMODEL, NH * DV, NH * DV, DMODEL, DMODEL, 0, 0, 0);

    rmsnorm_add_k<<<SEQ, 256>>>(proj, attn_post_w + i * DMODEL, s_state, s_state, DMODEL);

    // ===================== single-track feedforward =====================
    rmsnorm_k<<<SEQ, 256>>>(s_state, ff_pre_w + i * DMODEL, xn, DMODEL);
    gemm_tc<false,true,true,false><<<grid128(SEQ, FFI, 1), 256>>>(
        xn, ff_w1 + (size_t)i * DMODEL * FFI, ff_b1 + i * FFI, nullptr, ffh,
        SEQ, FFI, DMODEL, DMODEL, FFI, FFI, 0, 0, 0);
    gemm_tc<false,true,false,false><<<grid128(SEQ, DMODEL, 1), 256>>>(
        ffh, ff_w2 + (size_t)i * FFI * DMODEL, ff_b2 + i * DMODEL, nullptr, proj,
        SEQ, DMODEL, FFI, FFI, DMODEL, DMODEL, 0, 0, 0);
    rmsnorm_add_k<<<SEQ, 256>>>(proj, ff_post_w + i * DMODEL, s_state, s_state, DMODEL);

    // ===================== pairwise track (every other layer) =====================
    if (i % 2 == 0) {
      int j = pw_idx++;
      // attention over pairwise rows
      rmsnorm_k<<<NPAIR2, 128>>>(p_state, pw_attn_pre_w + j * DP, pxn, DP);
      gemm_tc<false,false,false,false><<<grid128(NPAIR2, 2 * DP, 1), 256>>>(
          pxn, pw_qk_w + (size_t)j * DP * 2 * DP, nullptr, nullptr, pqk,
          NPAIR2, 2 * DP, DP, DP, 2 * DP, 2 * DP, 0, 0, 0);
      gemm_tc<false,true,false,false><<<grid128(NPAIR2, DP, 1), 256>>>(
          pxn, pw_v_w + (size_t)j * DP * DP, pw_v_b + j * DP, nullptr, pv,
          NPAIR2, DP, DP, DP, DP, DP, 0, 0, 0);
      // psim[n] = pq[n] @ pk[n]^T  (batched NT; pq/pk interleaved in pqk, ld=256)
      gemm_tc<true,false,false,false><<<grid128(NP, NP, NP), 256>>>(
          pqk, pqk + DP, nullptr, nullptr, psim,
          NP, NP, DP, 2 * DP, 2 * DP, NP,
          (long)NP * 2 * DP, (long)NP * 2 * DP, (long)NP * NP);
      psoftmax_k<<<NPAIR2, NP>>>(psim);
      // pairwise = attn @ pv + pairwise   (batched NN with residual, in place)
      gemm_tc<false,false,false,true><<<grid128(NP, DP, NP), 256>>>(
          psim, pv, nullptr, p_state, p_state,
          NP, DP, NP, NP, DP, DP,
          (long)NP * NP, (long)NP * DP, (long)NP * DP);
      // pairwise feedforward (no sandwich): pairwise = relu(rms(x)W1+b1)W2+b2 + res
      rmsnorm_k<<<NPAIR2, 128>>>(p_state, pw_ff_pre_w + j * DP, pxn, DP);
      gemm_tc<false,true,true,false><<<grid128(NPAIR2, DPI, 1), 256>>>(
          pxn, pw_ff_w1 + (size_t)j * DP * DPI, pw_ff_b1 + j * DPI, nullptr, pffh,
          NPAIR2, DPI, DP, DP, DPI, DPI, 0, 0, 0);
      gemm_tc<false,true,false,true><<<grid128(NPAIR2, DP, 1), 256>>>(
          pffh, pw_ff_w2 + (size_t)j * DPI * DP, pw_ff_b2 + j * DP, p_state, p_state,
          NPAIR2, DP, DPI, DPI, DP, DP, 0, 0, 0);
    }
  }
}